// round 5
// baseline (speedup 1.0000x reference)
#include <cuda_runtime.h>
#include <cstdint>

// Problem constants
#define BB   64      // batch
#define TT   1024    // time steps
#define HH   256     // hidden per direction
#define DIN  136     // input features (68*2)
#define G4   1024    // 4*H
#define NBLK 64      // persistent blocks per direction
#define HB   (HH*BB) // 16384 floats of hidden state per direction

// ---------------- scratch (device globals; no allocations allowed) ----------------
__device__ __align__(16) float g_proj[2][(size_t)TT * G4 * BB]; // [dir][t][row][b]
__device__ __align__(16) float g_hs[(size_t)TT * 2 * HH * BB];  // [t][dir*H+j][b]
__device__ __align__(16) float g_hbuf[2][2][HB];                // [dir][parity][j][b]
__device__ __align__(128) unsigned g_bar_arrive[2][32];         // separate 128B lines
__device__ __align__(128) unsigned g_bar_epoch[2][32];

// ---------------- cp.async 16B (fetches via L2, bypasses L1) ----------------
__device__ __forceinline__ void cp_async16(float* smem_dst, const float* gsrc) {
    uint32_t s = (uint32_t)__cvta_generic_to_shared(smem_dst);
    asm volatile("cp.async.cg.shared.global [%0], [%1], 16;" :: "r"(s), "l"(gsrc));
}

// ---------------- activations ----------------
__device__ __forceinline__ float sigf(float x) {
    return 1.0f / (1.0f + __expf(-x));
}
__device__ __forceinline__ float tanh_fast(float x) {
    float xx = fminf(fmaxf(x, -10.0f), 10.0f);
    float e = __expf(2.0f * xx);
    return (e - 1.0f) / (e + 1.0f);
}

// ---------------- init: reset mutable state each launch (graph-replay safe) -------
__global__ void init_kernel() {
    int tid = threadIdx.x;
    float* hb = &g_hbuf[0][0][0];
    for (int i = tid; i < 2 * 2 * HB; i += 256) hb[i] = 0.0f;
    if (tid < 2) { g_bar_arrive[tid][0] = 0u; g_bar_epoch[tid][0] = 0u; }
}

// ---------------- input projection GEMM (R1 version, known-good) ------------------
__global__ void __launch_bounds__(128, 2) proj_kernel(
    const float* __restrict__ x,
    const float* __restrict__ wih_f, const float* __restrict__ wih_b,
    const float* __restrict__ bih_f, const float* __restrict__ bih_b)
{
    extern __shared__ float sm[];
    float* xs = sm;               // [136][68] transposed: xs[k][b]
    float* ws = sm + 136 * 68;    // [136][68] transposed: ws[k][r]

    const int t   = blockIdx.y;
    const int dir = blockIdx.z;
    const int r0  = blockIdx.x * 64;
    const float* w  = dir ? wih_b : wih_f;
    const float* bi = dir ? bih_b : bih_f;
    const int tid = threadIdx.x;

    for (int i = tid; i < 64 * 34; i += 128) {
        int b = i / 34, k4 = i - b * 34;
        float4 v = __ldg(((const float4*)(x + ((size_t)b * TT + t) * DIN)) + k4);
        int kb = k4 * 4;
        xs[(kb + 0) * 68 + b] = v.x;
        xs[(kb + 1) * 68 + b] = v.y;
        xs[(kb + 2) * 68 + b] = v.z;
        xs[(kb + 3) * 68 + b] = v.w;
    }
    for (int i = tid; i < 64 * 34; i += 128) {
        int r = i / 34, k4 = i - r * 34;
        float4 v = __ldg(((const float4*)(w + (size_t)(r0 + r) * DIN)) + k4);
        int kb = k4 * 4;
        ws[(kb + 0) * 68 + r] = v.x;
        ws[(kb + 1) * 68 + r] = v.y;
        ws[(kb + 2) * 68 + r] = v.z;
        ws[(kb + 3) * 68 + r] = v.w;
    }
    __syncthreads();

    const int tx = tid & 15;
    const int ty = tid >> 4;
    float acc[8][4];
#pragma unroll
    for (int q = 0; q < 8; q++)
#pragma unroll
        for (int j = 0; j < 4; j++) acc[q][j] = 0.0f;

#pragma unroll 4
    for (int k = 0; k < DIN; k++) {
        float4 xv = *(const float4*)(xs + k * 68 + tx * 4);
        float4 w0 = *(const float4*)(ws + k * 68 + ty * 8);
        float4 w1 = *(const float4*)(ws + k * 68 + ty * 8 + 4);
        float wv[8] = {w0.x, w0.y, w0.z, w0.w, w1.x, w1.y, w1.z, w1.w};
#pragma unroll
        for (int q = 0; q < 8; q++) {
            acc[q][0] += wv[q] * xv.x;
            acc[q][1] += wv[q] * xv.y;
            acc[q][2] += wv[q] * xv.z;
            acc[q][3] += wv[q] * xv.w;
        }
    }

    float* dst = g_proj[dir] + (size_t)t * G4 * BB;
#pragma unroll
    for (int q = 0; q < 8; q++) {
        int row = r0 + ty * 8 + q;
        float bias = __ldg(bi + row);
        float4 o = make_float4(acc[q][0] + bias, acc[q][1] + bias,
                               acc[q][2] + bias, acc[q][3] + bias);
        *(float4*)(dst + (size_t)row * BB + tx * 4) = o;
    }
}

// ---------------- persistent recurrent scan ----------------
// 128 blocks (64 fwd + 64 bwd), 256 threads, 1 CTA/SM.
// Block owns j' in [j0,j0+4) -> 16 gate rows. Thread = (row r, 4 batches).
// Full-K per thread (no split-k reduction). Weights in SMEM (broadcast LDS).
// h staged in two cp.async halves (overlap load with compute).
__global__ void __launch_bounds__(256, 1) scan_kernel(
    const float* __restrict__ whh_f, const float* __restrict__ whh_b,
    const float* __restrict__ bhh_f, const float* __restrict__ bhh_b)
{
    extern __shared__ float smem[];
    float*  h_s  = smem;                         // [256 k][64 b]            65536 B
    float4* wsm4 = (float4*)(smem + HB);         // [16 r][65 f4] (k4 0..63) 16640 B
    float*  gsm  = smem + HB + 16 * 65 * 4;      // [16 r][68]                4352 B

    const int dir = blockIdx.x >> 6;
    const int blk = blockIdx.x & 63;
    const int j0  = blk * 4;
    const float* whh = dir ? whh_b : whh_f;
    const float* bhh = dir ? bhh_b : bhh_f;
    const int tid = threadIdx.x;

    // compute-phase mapping
    const int r  = tid & 15;     // local gate row: gate g=r>>2, jj=r&3
    const int bg = tid >> 4;     // batches bg*4 .. +3
    const int grow = (r >> 2) * 256 + j0 + (r & 3);  // global W_hh row

    // load W_hh slice into SMEM: wsm4[r][k4] = whh[grow][4k4..4k4+3]
    for (int idx = tid; idx < 16 * 64; idx += 256) {
        int rr = idx >> 6, k4 = idx & 63;
        int growr = (rr >> 2) * 256 + j0 + (rr & 3);
        wsm4[rr * 65 + k4] = __ldg((const float4*)(whh + (size_t)growr * HH) + k4);
    }

    // state-phase mapping
    const int jj2 = tid >> 6;        // 0..3
    const int b2  = tid & 63;        // 0..63
    float bh[4];
#pragma unroll
    for (int g = 0; g < 4; g++) bh[g] = __ldg(bhh + g * 256 + j0 + jj2);

    float c = 0.0f;
    int p = 0;
    float* hbuf = &g_hbuf[dir][0][0];
    unsigned* arrive = &g_bar_arrive[dir][0];
    unsigned* epoch  = &g_bar_epoch[dir][0];
    __syncthreads();

    for (int s = 0; s < TT; ++s) {
        const int t = dir ? (TT - 1 - s) : s;

        // prefetch x-projection gate values (independent of h; hides under wait)
        float pf[4];
#pragma unroll
        for (int g = 0; g < 4; g++)
            pf[g] = __ldg(g_proj[dir] + ((size_t)t * G4 + g * 256 + j0 + jj2) * BB + b2);

        // wait: all producers published step s-1 (epoch >= s). Single hot line.
        if (s > 0 && tid == 0) {
            unsigned e;
            do {
                asm volatile("ld.global.acquire.gpu.u32 %0, [%1];"
                             : "=r"(e) : "l"(epoch) : "memory");
            } while (e < (unsigned)s);
        }
        __syncthreads();

        // stage h in two 32KB halves via cp.async (L2 path)
        {
            const float* src = hbuf + p * HB;
#pragma unroll
            for (int i = 0; i < 8; i++)
                cp_async16(h_s + (i * 256 + tid) * 4, src + (i * 256 + tid) * 4);
            asm volatile("cp.async.commit_group;" ::: "memory");
#pragma unroll
            for (int i = 8; i < 16; i++)
                cp_async16(h_s + (i * 256 + tid) * 4, src + (i * 256 + tid) * 4);
            asm volatile("cp.async.commit_group;" ::: "memory");
        }

        float a0 = 0.0f, a1 = 0.0f, a2 = 0.0f, a3 = 0.0f;
        const float4* wrow = wsm4 + r * 65;
        const float4* hp4  = (const float4*)h_s + bg;

        // half A: k = 0..127 (k4 0..31)
        asm volatile("cp.async.wait_group 1;" ::: "memory");
        __syncthreads();
#pragma unroll
        for (int k4 = 0; k4 < 32; k4++) {
            float4 wv = wrow[k4];
            const float4* hp = hp4 + (k4 << 6);     // k4*4 rows * 16 f4/row
            float4 h0 = hp[0], h1 = hp[16], h2 = hp[32], h3 = hp[48];
            a0 += wv.x * h0.x; a1 += wv.x * h0.y; a2 += wv.x * h0.z; a3 += wv.x * h0.w;
            a0 += wv.y * h1.x; a1 += wv.y * h1.y; a2 += wv.y * h1.z; a3 += wv.y * h1.w;
            a0 += wv.z * h2.x; a1 += wv.z * h2.y; a2 += wv.z * h2.z; a3 += wv.z * h2.w;
            a0 += wv.w * h3.x; a1 += wv.w * h3.y; a2 += wv.w * h3.z; a3 += wv.w * h3.w;
        }
        // half B: k = 128..255
        asm volatile("cp.async.wait_group 0;" ::: "memory");
        __syncthreads();
#pragma unroll
        for (int k4 = 32; k4 < 64; k4++) {
            float4 wv = wrow[k4];
            const float4* hp = hp4 + (k4 << 6);
            float4 h0 = hp[0], h1 = hp[16], h2 = hp[32], h3 = hp[48];
            a0 += wv.x * h0.x; a1 += wv.x * h0.y; a2 += wv.x * h0.z; a3 += wv.x * h0.w;
            a0 += wv.y * h1.x; a1 += wv.y * h1.y; a2 += wv.y * h1.z; a3 += wv.y * h1.w;
            a0 += wv.z * h2.x; a1 += wv.z * h2.y; a2 += wv.z * h2.z; a3 += wv.z * h2.w;
            a0 += wv.w * h3.x; a1 += wv.w * h3.y; a2 += wv.w * h3.z; a3 += wv.w * h3.w;
        }

        // publish complete gate pre-activations to gsm[r][b]
        *(float4*)(gsm + r * 68 + bg * 4) = make_float4(a0, a1, a2, a3);
        __syncthreads();

        // state phase: thread (jj2, b2) gathers 4 gates, applies LSTM cell
        float gv[4];
#pragma unroll
        for (int g = 0; g < 4; g++)
            gv[g] = pf[g] + bh[g] + gsm[(g * 4 + jj2) * 68 + b2];
        float i_ = sigf(gv[0]);
        float f_ = sigf(gv[1]);
        float g_ = tanh_fast(gv[2]);
        float o_ = sigf(gv[3]);
        c = f_ * c + i_ * g_;
        float h = o_ * tanh_fast(c);

        // publish h + hidden sequence
        hbuf[(p ^ 1) * HB + (j0 + jj2) * 64 + b2] = h;
        g_hs[((size_t)t * 512 + dir * HH + j0 + jj2) * BB + b2] = h;

        __syncthreads();   // all h stores of this CTA done before arrival
        if (tid == 0) {
            unsigned ticket;
            asm volatile("atom.global.add.acq_rel.gpu.u32 %0, [%1], 1;"
                         : "=r"(ticket) : "l"(arrive) : "memory");
            if (ticket == (unsigned)(s + 1) * NBLK - 1u) {
                asm volatile("st.global.release.gpu.u32 [%0], %1;"
                             :: "l"(epoch), "r"((unsigned)(s + 1)) : "memory");
            }
        }
        p ^= 1;
    }
}

// ---------------- final FC ----------------
__global__ void __launch_bounds__(320) fc_kernel(
    const float* __restrict__ fcw, const float* __restrict__ fcb,
    float* __restrict__ out)
{
    const int t = blockIdx.x;
    const int o = threadIdx.x / 64;  // 0..4
    const int b = threadIdx.x & 63;  // 0..63
    const float* hp = g_hs + (size_t)t * 512 * BB + b;
    const float* wp = fcw + o * 512;
    float acc = 0.0f;
#pragma unroll 8
    for (int j = 0; j < 512; j++)
        acc += hp[(size_t)j * BB] * __ldg(wp + j);
    out[((size_t)b * TT + t) * 5 + o] = acc + __ldg(fcb + o);
}

// ---------------- launch ----------------
extern "C" void kernel_launch(void* const* d_in, const int* in_sizes, int n_in,
                              void* d_out, int out_size)
{
    const float* x      = (const float*)d_in[0];
    const float* wih_f  = (const float*)d_in[1];
    const float* whh_f  = (const float*)d_in[2];
    const float* bih_f  = (const float*)d_in[3];
    const float* bhh_f  = (const float*)d_in[4];
    const float* wih_b  = (const float*)d_in[5];
    const float* whh_b  = (const float*)d_in[6];
    const float* bih_b  = (const float*)d_in[7];
    const float* bhh_b  = (const float*)d_in[8];
    const float* fcw    = (const float*)d_in[9];
    const float* fcb    = (const float*)d_in[10];
    float* out = (float*)d_out;

    const int proj_smem = 2 * 136 * 68 * (int)sizeof(float);        // 73,984 B
    const int scan_smem = HB * 4 + 16 * 65 * 16 + 16 * 68 * 4;      // 86,528 B
    cudaFuncSetAttribute(proj_kernel, cudaFuncAttributeMaxDynamicSharedMemorySize, proj_smem);
    cudaFuncSetAttribute(scan_kernel, cudaFuncAttributeMaxDynamicSharedMemorySize, scan_smem);

    init_kernel<<<1, 256>>>();

    dim3 pg(16, TT, 2);
    proj_kernel<<<pg, 128, proj_smem>>>(x, wih_f, wih_b, bih_f, bih_b);

    scan_kernel<<<2 * NBLK, 256, scan_smem>>>(whh_f, whh_b, bhh_f, bhh_b);

    fc_kernel<<<TT, 320>>>(fcw, fcb, out);
}

// round 7
// speedup vs baseline: 1.0872x; 1.0872x over previous
#include <cuda_runtime.h>
#include <cstdint>

// Problem constants
#define BB   64      // batch
#define TT   1024    // time steps
#define HH   256     // hidden per direction
#define DIN  136     // input features (68*2)
#define G4   1024    // 4*H
#define CL   8       // cluster size (CTAs per sync group)
#define BPC  8       // batches per cluster
#define JPC  32      // hidden units per CTA

// ---------------- scratch (device globals; no allocations allowed) ----------------
__device__ __align__(16) float g_proj[2][(size_t)TT * G4 * BB]; // [dir][t][row][b]
__device__ __align__(16) float g_hs[(size_t)TT * 2 * HH * BB];  // [t][dir*H+j][b]

// ---------------- activations ----------------
__device__ __forceinline__ float sigf(float x) {
    return 1.0f / (1.0f + __expf(-x));
}
__device__ __forceinline__ float tanh_fast(float x) {
    float xx = fminf(fmaxf(x, -10.0f), 10.0f);
    float e = __expf(2.0f * xx);
    return (e - 1.0f) / (e + 1.0f);
}

// ---------------- DSMEM: store float4 to peer rank's SMEM (same offset) -----------
__device__ __forceinline__ void st_cluster_f4(uint32_t laddr, uint32_t rank, float4 v) {
    asm volatile(
        "{\n\t"
        ".reg .b32 r;\n\t"
        "mapa.shared::cluster.u32 r, %0, %1;\n\t"
        "st.shared::cluster.v4.f32 [r], {%2, %3, %4, %5};\n\t"
        "}"
        :: "r"(laddr), "r"(rank), "f"(v.x), "f"(v.y), "f"(v.z), "f"(v.w) : "memory");
}

// ---------------- input projection GEMM (R1 version, known-good) ------------------
__global__ void __launch_bounds__(128, 2) proj_kernel(
    const float* __restrict__ x,
    const float* __restrict__ wih_f, const float* __restrict__ wih_b,
    const float* __restrict__ bih_f, const float* __restrict__ bih_b)
{
    extern __shared__ float sm[];
    float* xs = sm;               // [136][68] transposed: xs[k][b]
    float* ws = sm + 136 * 68;    // [136][68] transposed: ws[k][r]

    const int t   = blockIdx.y;
    const int dir = blockIdx.z;
    const int r0  = blockIdx.x * 64;
    const float* w  = dir ? wih_b : wih_f;
    const float* bi = dir ? bih_b : bih_f;
    const int tid = threadIdx.x;

    for (int i = tid; i < 64 * 34; i += 128) {
        int b = i / 34, k4 = i - b * 34;
        float4 v = __ldg(((const float4*)(x + ((size_t)b * TT + t) * DIN)) + k4);
        int kb = k4 * 4;
        xs[(kb + 0) * 68 + b] = v.x;
        xs[(kb + 1) * 68 + b] = v.y;
        xs[(kb + 2) * 68 + b] = v.z;
        xs[(kb + 3) * 68 + b] = v.w;
    }
    for (int i = tid; i < 64 * 34; i += 128) {
        int r = i / 34, k4 = i - r * 34;
        float4 v = __ldg(((const float4*)(w + (size_t)(r0 + r) * DIN)) + k4);
        int kb = k4 * 4;
        ws[(kb + 0) * 68 + r] = v.x;
        ws[(kb + 1) * 68 + r] = v.y;
        ws[(kb + 2) * 68 + r] = v.z;
        ws[(kb + 3) * 68 + r] = v.w;
    }
    __syncthreads();

    const int tx = tid & 15;
    const int ty = tid >> 4;
    float acc[8][4];
#pragma unroll
    for (int q = 0; q < 8; q++)
#pragma unroll
        for (int j = 0; j < 4; j++) acc[q][j] = 0.0f;

#pragma unroll 4
    for (int k = 0; k < DIN; k++) {
        float4 xv = *(const float4*)(xs + k * 68 + tx * 4);
        float4 w0 = *(const float4*)(ws + k * 68 + ty * 8);
        float4 w1 = *(const float4*)(ws + k * 68 + ty * 8 + 4);
        float wv[8] = {w0.x, w0.y, w0.z, w0.w, w1.x, w1.y, w1.z, w1.w};
#pragma unroll
        for (int q = 0; q < 8; q++) {
            acc[q][0] += wv[q] * xv.x;
            acc[q][1] += wv[q] * xv.y;
            acc[q][2] += wv[q] * xv.z;
            acc[q][3] += wv[q] * xv.w;
        }
    }

    float* dst = g_proj[dir] + (size_t)t * G4 * BB;
#pragma unroll
    for (int q = 0; q < 8; q++) {
        int row = r0 + ty * 8 + q;
        float bias = __ldg(bi + row);
        float4 o = make_float4(acc[q][0] + bias, acc[q][1] + bias,
                               acc[q][2] + bias, acc[q][3] + bias);
        *(float4*)(dst + (size_t)row * BB + tx * 4) = o;
    }
}

// ---------------- clustered recurrent scan ----------------
// 128 CTAs = 16 clusters of 8. Cluster = (dir, batch-group of 8 batches).
// CTA rank owns j in [rank*32, rank*32+32) -> 128 gate rows x 8 batches.
// h double-buffered in SMEM; all-gather via DSMEM float4 stores.
// One barrier.cluster per step (also serves as exit barrier on last step).
__global__ void __launch_bounds__(256, 1) __cluster_dims__(CL, 1, 1)
scan_kernel(const float* __restrict__ whh_f, const float* __restrict__ whh_b,
            const float* __restrict__ bhh_f, const float* __restrict__ bhh_b)
{
    extern __shared__ float smem[];
    float* h_s = smem;                    // [2][256 k][8 b]      16384 B
    float* red = smem + 2 * 256 * 8;      // [8 w][8 b][132 r]    33792 B

    const int cid  = blockIdx.x >> 3;     // cluster 0..15
    const int rank = blockIdx.x & 7;      // rank in cluster
    const int dir  = cid >> 3;            // 0..1
    const int b0   = (cid & 7) * BPC;     // batch base
    const int j0   = rank * JPC;          // hidden base
    const float* whh = dir ? whh_b : whh_f;
    const float* bhh = dir ? bhh_b : bhh_f;
    const int tid  = threadIdx.x;
    const int w    = tid >> 5;            // warp = k-slice [w*32, w*32+32)
    const int lane = tid & 31;            // lane -> 4 local gate rows

    // W_hh in registers: wreg[q][kk] = whh[grow(lane*4+q)][w*32+kk]
    float wreg[4][32];
#pragma unroll
    for (int q = 0; q < 4; q++) {
        int rl = lane * 4 + q;                       // local row 0..127
        int grow = (rl >> 5) * 256 + j0 + (rl & 31); // gate*256 + j
        const float4* src = (const float4*)(whh + (size_t)grow * HH + w * 32);
#pragma unroll
        for (int k4 = 0; k4 < 8; k4++) {
            float4 v = __ldg(src + k4);
            wreg[q][k4 * 4 + 0] = v.x; wreg[q][k4 * 4 + 1] = v.y;
            wreg[q][k4 * 4 + 2] = v.z; wreg[q][k4 * 4 + 3] = v.w;
        }
    }

    // state-phase mapping: thread owns (jj, b); note (jj*8+b) == tid
    const int jj = tid >> 3;              // 0..31
    const int b  = tid & 7;               // 0..7
    float bh[4];
#pragma unroll
    for (int g = 0; g < 4; g++) bh[g] = __ldg(bhh + g * 256 + j0 + jj);

    // zero h buffer 0, then cluster-wide sync before first step
    for (int i = tid; i < 2048; i += 256) h_s[i] = 0.0f;
    __syncthreads();
    asm volatile("barrier.cluster.arrive.aligned;" ::: "memory");
    asm volatile("barrier.cluster.wait.aligned;" ::: "memory");

    float c = 0.0f;

    for (int s = 0; s < TT; ++s) {
        const int t = dir ? (TT - 1 - s) : s;
        const int p = s & 1;

        // prefetch x-projection gate values (DRAM; hides under GEMM)
        float pf[4];
#pragma unroll
        for (int g = 0; g < 4; g++)
            pf[g] = __ldg(g_proj[dir] + ((size_t)t * G4 + g * 256 + j0 + jj) * BB + b0 + b);

        // k-slice GEMM: 4 local rows x 8 batches over 32 k (weights in regs)
        float acc[4][8];
#pragma unroll
        for (int q = 0; q < 4; q++)
#pragma unroll
            for (int i = 0; i < 8; i++) acc[q][i] = 0.0f;

        const float* hrow = h_s + p * 2048 + w * 32 * 8;
#pragma unroll
        for (int kk = 0; kk < 32; kk++) {
            float4 hlo = *(const float4*)(hrow + kk * 8);
            float4 hhi = *(const float4*)(hrow + kk * 8 + 4);
#pragma unroll
            for (int q = 0; q < 4; q++) {
                float wq = wreg[q][kk];
                acc[q][0] += wq * hlo.x; acc[q][1] += wq * hlo.y;
                acc[q][2] += wq * hlo.z; acc[q][3] += wq * hlo.w;
                acc[q][4] += wq * hhi.x; acc[q][5] += wq * hhi.y;
                acc[q][6] += wq * hhi.z; acc[q][7] += wq * hhi.w;
            }
        }

        // split-k partials: red[w][b][r] padded to 132 (conflict-free both phases)
#pragma unroll
        for (int bb = 0; bb < 8; bb++) {
            float4 v = make_float4(acc[0][bb], acc[1][bb], acc[2][bb], acc[3][bb]);
            *(float4*)(red + ((w << 3) + bb) * 132 + lane * 4) = v;
        }
        __syncthreads();

        // state phase: reduce 8 k-slices per gate, apply LSTM cell
        float gv[4];
#pragma unroll
        for (int g = 0; g < 4; g++) {
            float v = pf[g] + bh[g];
#pragma unroll
            for (int wi = 0; wi < 8; wi++)
                v += red[((wi << 3) + b) * 132 + (g << 5) + jj];
            gv[g] = v;
        }
        float i_ = sigf(gv[0]);
        float f_ = sigf(gv[1]);
        float g_ = tanh_fast(gv[2]);
        float o_ = sigf(gv[3]);
        c = f_ * c + i_ * g_;
        float h = o_ * tanh_fast(c);

        // store hidden sequence (global) + own h into local next buffer
        g_hs[((size_t)t * 512 + dir * 256 + j0 + jj) * BB + b0 + b] = h;
        h_s[(p ^ 1) * 2048 + j0 * 8 + tid] = h;     // own slice is contiguous: idx==tid
        __syncthreads();

        // all-gather own 256-float slice to 7 peers (64 float4 chunks each)
        {
            uint32_t lbase = (uint32_t)__cvta_generic_to_shared(
                h_s + (p ^ 1) * 2048 + j0 * 8);
            const float4* srcv = (const float4*)(h_s + (p ^ 1) * 2048 + j0 * 8);
            for (int i = tid; i < 7 * 64; i += 256) {
                int chunk = i & 63;
                uint32_t dr = (uint32_t)((rank + 1 + (i >> 6)) & 7);
                st_cluster_f4(lbase + chunk * 16, dr, srcv[chunk]);
            }
        }

        // cluster barrier: orders DSMEM stores, gates next step, guards exit
        asm volatile("barrier.cluster.arrive.aligned;" ::: "memory");
        asm volatile("barrier.cluster.wait.aligned;" ::: "memory");
    }
}

// ---------------- final FC ----------------
__global__ void __launch_bounds__(320) fc_kernel(
    const float* __restrict__ fcw, const float* __restrict__ fcb,
    float* __restrict__ out)
{
    const int t = blockIdx.x;
    const int o = threadIdx.x / 64;  // 0..4
    const int b = threadIdx.x & 63;  // 0..63
    const float* hp = g_hs + (size_t)t * 512 * BB + b;
    const float* wp = fcw + o * 512;
    float acc = 0.0f;
#pragma unroll 8
    for (int j = 0; j < 512; j++)
        acc += hp[(size_t)j * BB] * __ldg(wp + j);
    out[((size_t)b * TT + t) * 5 + o] = acc + __ldg(fcb + o);
}

// ---------------- launch ----------------
extern "C" void kernel_launch(void* const* d_in, const int* in_sizes, int n_in,
                              void* d_out, int out_size)
{
    const float* x      = (const float*)d_in[0];
    const float* wih_f  = (const float*)d_in[1];
    const float* whh_f  = (const float*)d_in[2];
    const float* bih_f  = (const float*)d_in[3];
    const float* bhh_f  = (const float*)d_in[4];
    const float* wih_b  = (const float*)d_in[5];
    const float* whh_b  = (const float*)d_in[6];
    const float* bih_b  = (const float*)d_in[7];
    const float* bhh_b  = (const float*)d_in[8];
    const float* fcw    = (const float*)d_in[9];
    const float* fcb    = (const float*)d_in[10];
    float* out = (float*)d_out;

    const int proj_smem = 2 * 136 * 68 * (int)sizeof(float);                  // 73,984 B
    const int scan_smem = (2 * 256 * 8 + 8 * 8 * 132) * (int)sizeof(float);   // 50,176 B
    cudaFuncSetAttribute(proj_kernel, cudaFuncAttributeMaxDynamicSharedMemorySize, proj_smem);
    cudaFuncSetAttribute(scan_kernel, cudaFuncAttributeMaxDynamicSharedMemorySize, scan_smem);

    dim3 pg(16, TT, 2);
    proj_kernel<<<pg, 128, proj_smem>>>(x, wih_f, wih_b, bih_f, bih_b);

    scan_kernel<<<128, 256, scan_smem>>>(whh_f, whh_b, bhh_f, bhh_b);

    fc_kernel<<<TT, 320>>>(fcw, fcb, out);
}